// round 7
// baseline (speedup 1.0000x reference)
#include <cuda_runtime.h>
#include <cstdint>

#define N_VOX   262144
#define M_PAIRS 131072
#define K_OFF   27
#define C       32
#define CPAD    36        // row stride in floats: 16B pad -> halves hit disjoint banks

// ---------------------------------------------------------------------------
// Kernel 1: out[n][c] = bias[c]  (bias add commutes with the scatter-adds)
// ---------------------------------------------------------------------------
__global__ void bias_init_kernel(float* __restrict__ out,
                                 const float* __restrict__ bias)
{
    int t = blockIdx.x * blockDim.x + threadIdx.x;
    const int total4 = N_VOX * (C / 4);
    if (t < total4) {
        const float4* b4 = (const float4*)bias;
        float4* o4 = (float4*)out;
        o4[t] = b4[t & 7];
    }
}

// ---------------------------------------------------------------------------
// Kernel 2: staged gather -> smem -> f32x2 GEMM (2 pairs/warp) -> red.v2.
//
//   Stage:  256 rows gathered coalesced (8 lanes x float4 per row) into
//           padded smem rows (stride 36 floats).
//   Math:   each 16-lane half-warp owns one pair; lane covers 2 channels
//           (one f32x2 accumulator). Each LDS.128 feeds TWO pairs ->
//           4 LDS/pair instead of 8; padding makes the 2-address LDS
//           conflict-free.
//   Scatter: red.global.add.v2.f32 per lane (contiguous 128B per pair).
// ---------------------------------------------------------------------------
#define THREADS          256
#define WARPS_PER_BLOCK  8
#define PAIRS_PER_BLOCK  256
#define PAIRS_PER_WARP   (PAIRS_PER_BLOCK / WARPS_PER_BLOCK)   // 32
#define STEPS            (PAIRS_PER_WARP / 2)                  // 16 (2 pairs/step)

__global__ __launch_bounds__(THREADS)
void scatter_gemm_kernel(const float* __restrict__ input,
                         const float* __restrict__ kernel,
                         const int*   __restrict__ in_map,
                         const int*   __restrict__ out_map,
                         float*       __restrict__ out)
{
    __shared__ float srow[PAIRS_PER_BLOCK][CPAD];    // 36 KB staged rows

    const int k     = blockIdx.y;
    const int lane  = threadIdx.x & 31;
    const int warp  = threadIdx.x >> 5;
    const int half  = lane >> 4;          // which pair of the step
    const int chalf = lane & 15;          // channel pair: covers 2*chalf, 2*chalf+1

    const int tile = blockIdx.x * PAIRS_PER_BLOCK;
    const int* im  = in_map  + k * M_PAIRS + tile;
    const int* om  = out_map + k * M_PAIRS + tile;

    // ---- Stage: 256 rows x 8 quads, coalesced; 8 float4 per thread.
    #pragma unroll
    for (int i = 0; i < (PAIRS_PER_BLOCK * (C / 4)) / THREADS; i++) {
        int q  = threadIdx.x + i * THREADS;
        int pr = q >> 3;
        int qq = q & 7;
        int irow = __ldg(im + pr);
        ((float4*)&srow[pr][0])[qq] =
            __ldg((const float4*)(input + (size_t)irow * C) + qq);
    }

    // ---- Weights: lane's 2 output channels, packed f32x2 per input channel.
    const float* Wk = kernel + k * C * C;
    unsigned long long wp[C];
    #pragma unroll
    for (int i = 0; i < C; i++) {
        float2 w2 = __ldg((const float2*)(Wk + i * C) + chalf);
        asm("mov.b64 %0, {%1, %2};" : "=l"(wp[i]) : "f"(w2.x), "f"(w2.y));
    }

    __syncthreads();

    const int pbase = warp * PAIRS_PER_WARP;

    #pragma unroll 4
    for (int t = 0; t < STEPS; t++) {
        const int pr   = pbase + 2 * t + half;
        const int orow = __ldg(om + pr);        // 2 distinct addrs per warp

        const float4* r4 = (const float4*)&srow[pr][0];

        unsigned long long acc = 0ULL;          // packed (0.f, 0.f)
        #pragma unroll
        for (int j = 0; j < C / 4; j++) {
            float4 a = r4[j];                   // 2-addr LDS.128, conflict-free
            unsigned long long ax, ay, az, aw;
            asm("mov.b64 %0, {%1, %1};" : "=l"(ax) : "f"(a.x));
            asm("mov.b64 %0, {%1, %1};" : "=l"(ay) : "f"(a.y));
            asm("mov.b64 %0, {%1, %1};" : "=l"(az) : "f"(a.z));
            asm("mov.b64 %0, {%1, %1};" : "=l"(aw) : "f"(a.w));
            asm("fma.rn.f32x2 %0, %1, %2, %0;" : "+l"(acc) : "l"(ax), "l"(wp[4 * j + 0]));
            asm("fma.rn.f32x2 %0, %1, %2, %0;" : "+l"(acc) : "l"(ay), "l"(wp[4 * j + 1]));
            asm("fma.rn.f32x2 %0, %1, %2, %0;" : "+l"(acc) : "l"(az), "l"(wp[4 * j + 2]));
            asm("fma.rn.f32x2 %0, %1, %2, %0;" : "+l"(acc) : "l"(aw), "l"(wp[4 * j + 3]));
        }
        float lo, hi;
        asm("mov.b64 {%0, %1}, %2;" : "=f"(lo), "=f"(hi) : "l"(acc));

        float* dst = out + (size_t)orow * C + 2 * chalf;   // 8B aligned
        asm volatile("red.global.add.v2.f32 [%0], {%1, %2};"
                     :: "l"(dst), "f"(lo), "f"(hi) : "memory");
    }
}

// ---------------------------------------------------------------------------
// Launch
// ---------------------------------------------------------------------------
extern "C" void kernel_launch(void* const* d_in, const int* in_sizes, int n_in,
                              void* d_out, int out_size)
{
    const float* input   = (const float*)d_in[0];
    const float* kernelw = (const float*)d_in[1];
    const float* bias    = (const float*)d_in[2];
    const int*   in_map  = (const int*)  d_in[3];
    const int*   out_map = (const int*)  d_in[4];
    float*       out     = (float*)d_out;

    const int total4 = N_VOX * (C / 4);
    bias_init_kernel<<<(total4 + 255) / 256, 256>>>(out, bias);

    dim3 grid(M_PAIRS / PAIRS_PER_BLOCK, K_OFF);
    scatter_gemm_kernel<<<grid, THREADS>>>(input, kernelw, in_map, out_map, out);
}